// round 9
// baseline (speedup 1.0000x reference)
#include <cuda_runtime.h>
#include <cstdint>

// ============================================================================
// FourierKARTLayer, 3-kernel: prep -> angles -> K2 (sincos + GEMM2 d-half).
//   K2 grid 512 = 256 token-tiles(8) x 2 d-halves; full F in smem per block;
//   disjoint V writes. R9: W2 inner-loop LDG software-pipelined (depth 2)
//   to hide the 234-cyc L2 hit (L1 can't cache W2: 4x48KB smem carveout).
// ============================================================================

#define D_INF   256
#define D_OUTF  64
#define NQ      128
#define NK      6
#define NTOK    2048
#define TPB     256
#define TOKB    8
#define NFEAT   1536

__device__ float g_WcT[D_INF * NQ];      // [i][q]
__device__ float g_W2[NFEAT * D_OUTF];   // [f][d]
__device__ float g_ang[NTOK * NQ];       // [tok][q]

using u64 = unsigned long long;

__device__ __forceinline__ u64 pack2(float x, float y) {
    u64 r; asm("mov.b64 %0, {%1, %2};" : "=l"(r) : "f"(x), "f"(y)); return r;
}
__device__ __forceinline__ u64 fma2(u64 a, u64 b, u64 c) {
    u64 d; asm("fma.rn.f32x2 %0, %1, %2, %3;" : "=l"(d) : "l"(a), "l"(b), "l"(c)); return d;
}
__device__ __forceinline__ float2 unpack2(u64 a) {
    float2 f; asm("mov.b64 {%0, %1}, %2;" : "=f"(f.x), "=f"(f.y) : "l"(a)); return f;
}
__device__ __forceinline__ u64 add2(u64 a, u64 b) {
    u64 d; asm("add.rn.f32x2 %0, %1, %2;" : "=l"(d) : "l"(a), "l"(b)); return d;
}

// ----------------------------------------------------------------------------
// K0: prep (W2 fold + WcT transpose). grid 512 x 256.
// ----------------------------------------------------------------------------
__global__ void prep_kernel(const float* __restrict__ Wc_w,
                            const float* __restrict__ A,
                            const float* __restrict__ Bp) {
    int n = blockIdx.x * blockDim.x + threadIdx.x;
    if (n < D_OUTF * NQ * NK) {                  // 49152, coalesced A/Bp reads
        int k  = n % NK;
        int dq = n / NK;
        int q  = dq & (NQ - 1);
        int d  = dq >> 7;
        float a  = __ldg(A + n);
        float bp = __ldg(Bp + n);
        float nr = rintf(bp * 0.15915494309189535f);
        float br = fmaf(nr, -6.283185307179586f, bp);
        float sb, cb;
        __sincosf(br, &sb, &cb);
        g_W2[(k * NQ + q) * D_OUTF + d]        = a * cb;   // sin-row coeff
        g_W2[((k + NK) * NQ + q) * D_OUTF + d] = a * sb;   // cos-row coeff
    }
    if (n < D_INF * NQ) {
        int q = n & (NQ - 1);
        int i = n >> 7;
        g_WcT[n] = Wc_w[q * D_INF + i];
    }
}

// ----------------------------------------------------------------------------
// K1: angles. grid 256 x 256 (8 tokens per block).
// ----------------------------------------------------------------------------
__global__ void __launch_bounds__(TPB) angles_kernel(
    const float* __restrict__ X0,
    const float* __restrict__ t,
    const float* __restrict__ Wc_b,
    const float* __restrict__ w) {

    __shared__ float Xs[D_INF * TOKB];     // [256 i][8 tok]
    __shared__ u64   E[4 * 2 * NQ];        // [pair][ih][q]

    const int tid = threadIdx.x;
    const int g0  = blockIdx.x * TOKB;
    const float tb = t[g0 >> 10];

    {
        int tok = tid >> 5;
        int seg = tid & 31;
        const float4* src = (const float4*)(X0 + (size_t)(g0 + tok) * D_INF + seg * 8);
        float4 v0 = src[0];
        float4 v1 = src[1];
        int i0 = seg * 8;
        Xs[(i0 + 0) * TOKB + tok] = v0.x;
        Xs[(i0 + 1) * TOKB + tok] = v0.y;
        Xs[(i0 + 2) * TOKB + tok] = v0.z;
        Xs[(i0 + 3) * TOKB + tok] = v0.w;
        Xs[(i0 + 4) * TOKB + tok] = v1.x;
        Xs[(i0 + 5) * TOKB + tok] = v1.y;
        Xs[(i0 + 6) * TOKB + tok] = v1.z;
        Xs[(i0 + 7) * TOKB + tok] = v1.w;
    }
    __syncthreads();

    {
        const int ih = tid >> 7;
        const int q  = tid & (NQ - 1);
        u64 acc[4] = {0ULL, 0ULL, 0ULL, 0ULL};
        #pragma unroll 8
        for (int s = 0; s < D_INF / 2; s++) {
            int i = ih * (D_INF / 2) + s;
            float wv = __ldg(g_WcT + i * NQ + q);
            u64 wd = pack2(wv, wv);
            ulonglong2 xa = *(const ulonglong2*)(Xs + i * TOKB);
            ulonglong2 xb = *(const ulonglong2*)(Xs + i * TOKB + 4);
            acc[0] = fma2(xa.x, wd, acc[0]);
            acc[1] = fma2(xa.y, wd, acc[1]);
            acc[2] = fma2(xb.x, wd, acc[2]);
            acc[3] = fma2(xb.y, wd, acc[3]);
        }
        #pragma unroll
        for (int p = 0; p < 4; p++)
            E[(p * 2 + ih) * NQ + q] = acc[p];
    }
    __syncthreads();

    {
        const int q  = tid & (NQ - 1);
        const int th = tid >> 7;
        float init = fmaf(w[q], tb, Wc_b[q]);
        u64 bi = pack2(init, init);
        int p0 = th * 2;
        u64 s0 = add2(add2(E[(p0 * 2 + 0) * NQ + q], E[(p0 * 2 + 1) * NQ + q]), bi);
        u64 s1 = add2(add2(E[((p0 + 1) * 2 + 0) * NQ + q], E[((p0 + 1) * 2 + 1) * NQ + q]), bi);
        float2 a01 = unpack2(s0);
        float2 a23 = unpack2(s1);
        float* ap = g_ang + (size_t)(g0 + th * 4) * NQ + q;
        ap[0 * NQ] = a01.x;
        ap[1 * NQ] = a01.y;
        ap[2 * NQ] = a23.x;
        ap[3 * NQ] = a23.y;
    }
}

// ----------------------------------------------------------------------------
// K2: sincos + GEMM2 d-half. grid 512 = 256 tiles x 2 d-halves, 4 CTAs/SM.
// smem 48KB: Fs [1536 f][8 tok]; R (32KB) aliases Fs for the reduction.
// W2 LDG double-buffered in registers (prefetch distance 2).
// ----------------------------------------------------------------------------
__global__ void __launch_bounds__(TPB, 4) k2_kernel(float* __restrict__ V) {
    extern __shared__ float smem[];
    float* Fs = smem;                  // [1536 f][8 tok]
    u64*   R  = (u64*)smem;            // [32 fs][128 col] swizzled

    const int tid  = threadIdx.x;
    const int tile = blockIdx.x >> 1;
    const int h    = blockIdx.x & 1;   // d-half: d in [h*32, h*32+32)
    const int g0   = tile * TOKB;

    // ---- sincos + harmonic recurrence -> full F -------------------------
    {
        const int q  = tid & (NQ - 1);
        const int th = tid >> 7;        // tokens th*4 .. th*4+3
        const float* ap = g_ang + (size_t)(g0 + th * 4) * NQ + q;
        float ang[4] = {ap[0 * NQ], ap[1 * NQ], ap[2 * NQ], ap[3 * NQ]};

        float sv[4], cv[4], sk[4], ck[4];
        #pragma unroll
        for (int j = 0; j < 4; j++) {
            float nr = rintf(ang[j] * 0.15915494309189535f);
            float ar = fmaf(nr, -6.283185307179586f, ang[j]);
            __sincosf(ar, &sv[j], &cv[j]);
            sk[j] = sv[j]; ck[j] = cv[j];
        }
        float* base = Fs + q * TOKB + th * 4;
        #pragma unroll
        for (int k = 0; k < NK; k++) {
            *(float4*)(base + (k * NQ) * TOKB)        = make_float4(sk[0], sk[1], sk[2], sk[3]);
            *(float4*)(base + ((k + NK) * NQ) * TOKB) = make_float4(ck[0], ck[1], ck[2], ck[3]);
            #pragma unroll
            for (int j = 0; j < 4; j++) {
                float ns = fmaf(sk[j], cv[j], ck[j] * sv[j]);
                float nc = fmaf(ck[j], cv[j], -sk[j] * sv[j]);
                sk[j] = ns; ck[j] = nc;
            }
        }
    }
    __syncthreads();

    // ---- GEMM2: thread = (fs 0..31, dg 0..7), tile 8 tok x 4 d ----------
    // W2 rows prefetched 2 iterations ahead (covers L2 hit latency).
    const int fs = tid >> 3;           // f = j*32 + fs
    const int dg = tid & 7;            // d = h*32 + dg*4 + dd
    u64 acc[16];                       // [pair 4][dd 4]
    #pragma unroll
    for (int k = 0; k < 16; k++) acc[k] = 0ULL;

    const int NJ = NFEAT / 32;         // 48
    const float* w2base = g_W2 + h * 32 + dg * 4 + fs * D_OUTF;   // + j*32*64
    float4 wv[2];
    wv[0] = __ldg((const float4*)(w2base));
    wv[1] = __ldg((const float4*)(w2base + 2048));

    for (int j = 0; j < NJ; j++) {
        const int b = j & 1;
        float4 cw = wv[b];                         // consume, then refill slot
        int jn = (j + 2 < NJ) ? (j + 2) : j;       // clamped prefetch
        wv[b] = __ldg((const float4*)(w2base + jn * 2048));

        const float* frow = Fs + (j * 32 + fs) * TOKB;
        ulonglong2 f01 = *(const ulonglong2*)frow;          // (t0,t1),(t2,t3)
        ulonglong2 f23 = *(const ulonglong2*)(frow + 4);    // (t4,t5),(t6,t7)
        u64 fp[4] = {f01.x, f01.y, f23.x, f23.y};
        float wa[4] = {cw.x, cw.y, cw.z, cw.w};
        #pragma unroll
        for (int dd = 0; dd < 4; dd++) {
            u64 wd = pack2(wa[dd], wa[dd]);
            #pragma unroll
            for (int p = 0; p < 4; p++)
                acc[p * 4 + dd] = fma2(fp[p], wd, acc[p * 4 + dd]);
        }
    }

    // ---- Reduce over 32 f-slices (swizzled; R aliases Fs) ---------------
    __syncthreads();
    #pragma unroll
    for (int p = 0; p < 4; p++)
        #pragma unroll
        for (int dd = 0; dd < 4; dd++) {
            int col = (p * 32 + dg * 4 + dd + fs * 4) & 127;
            R[fs * 128 + col] = acc[p * 4 + dd];
        }
    __syncthreads();

    if (tid < 128) {
        int od = tid;                  // p = od>>5, c = od&31
        u64 s = 0ULL;
        #pragma unroll
        for (int j = 0; j < 32; j++)
            s = add2(s, R[j * 128 + ((od + j * 4) & 127)]);
        float2 v = unpack2(s);
        int p = od >> 5;
        int c = od & 31;
        float* vp = V + (size_t)(g0 + 2 * p) * D_OUTF + h * 32 + c;
        vp[0]      = v.x;
        vp[D_OUTF] = v.y;
    }
}

// ----------------------------------------------------------------------------
extern "C" void kernel_launch(void* const* d_in, const int* in_sizes, int n_in,
                              void* d_out, int out_size) {
    const float* X0   = (const float*)d_in[0];
    const float* t    = (const float*)d_in[1];
    const float* Wc_w = (const float*)d_in[2];
    const float* Wc_b = (const float*)d_in[3];
    const float* w    = (const float*)d_in[4];
    const float* A    = (const float*)d_in[5];
    const float* Bp   = (const float*)d_in[6];
    float* V = (float*)d_out;

    const int smem2 = 49152;           // Fs 48KB (R aliases)
    cudaFuncSetAttribute(k2_kernel, cudaFuncAttributeMaxDynamicSharedMemorySize, smem2);

    prep_kernel<<<512, 256>>>(Wc_w, A, Bp);
    angles_kernel<<<NTOK / TOKB, TPB>>>(X0, t, Wc_b, w);
    k2_kernel<<<2 * NTOK / TOKB, TPB, smem2>>>(V);
}

// round 10
// speedup vs baseline: 1.1185x; 1.1185x over previous
#include <cuda_runtime.h>
#include <cstdint>

// ============================================================================
// FourierKARTLayer, cluster co-block version (2 launches):
//   K0 prep: W2 fold + WcT transpose.
//   K1 main: grid 512 = 256 token-tiles x 2 d-halves, cluster_dims(2):
//     - pair i-splits GEMM1 (128 i's each), partials exchanged via DSMEM
//     - each block: sincos -> full F (48KB smem), GEMM2 over its 32 d-columns
//     - disjoint V writes (no atomics)
// ============================================================================

#define D_INF   256
#define D_OUTF  64
#define NQ      128
#define NK      6
#define NTOK    2048
#define TPB     256
#define TOKB    8
#define NFEAT   1536

__device__ float g_WcT[D_INF * NQ];      // [i][q]
__device__ float g_W2[NFEAT * D_OUTF];   // [f][d]

using u64 = unsigned long long;

__device__ __forceinline__ u64 pack2(float x, float y) {
    u64 r; asm("mov.b64 %0, {%1, %2};" : "=l"(r) : "f"(x), "f"(y)); return r;
}
__device__ __forceinline__ u64 fma2(u64 a, u64 b, u64 c) {
    u64 d; asm("fma.rn.f32x2 %0, %1, %2, %3;" : "=l"(d) : "l"(a), "l"(b), "l"(c)); return d;
}
__device__ __forceinline__ float2 unpack2(u64 a) {
    float2 f; asm("mov.b64 {%0, %1}, %2;" : "=f"(f.x), "=f"(f.y) : "l"(a)); return f;
}
__device__ __forceinline__ u64 add2(u64 a, u64 b) {
    u64 d; asm("add.rn.f32x2 %0, %1, %2;" : "=l"(d) : "l"(a), "l"(b)); return d;
}
__device__ __forceinline__ uint32_t smem_u32(const void* p) {
    return (uint32_t)__cvta_generic_to_shared(p);
}

// ----------------------------------------------------------------------------
// K0: prep (W2 fold + WcT transpose). grid 192 x 256 = 49152 threads.
// ----------------------------------------------------------------------------
__global__ void prep_kernel(const float* __restrict__ Wc_w,
                            const float* __restrict__ A,
                            const float* __restrict__ Bp) {
    int n = blockIdx.x * blockDim.x + threadIdx.x;          // 0..49151
    {
        int k  = n % NK;
        int dq = n / NK;
        int q  = dq & (NQ - 1);
        int d  = dq >> 7;
        float a  = __ldg(A + n);
        float bp = __ldg(Bp + n);
        float nr = rintf(bp * 0.15915494309189535f);
        float br = fmaf(nr, -6.283185307179586f, bp);
        float sb, cb;
        __sincosf(br, &sb, &cb);
        g_W2[(k * NQ + q) * D_OUTF + d]        = a * cb;    // sin-row coeff
        g_W2[((k + NK) * NQ + q) * D_OUTF + d] = a * sb;    // cos-row coeff
    }
    if (n < D_INF * NQ) {
        int q = n & (NQ - 1);
        int i = n >> 7;
        g_WcT[n] = Wc_w[q * D_INF + i];
    }
}

// ----------------------------------------------------------------------------
// K1: main. grid 512, cluster 2. Co-blocks (tile, h=0/1):
//   - block h handles i in [h*128, h*128+128) of GEMM1, d in [h*32, h*32+32).
// smem 48KB, phase-aliased:
//   phase 1-3: Xs [0,4K) | E [4K,12K) | Epeer [12K,16K)
//   phase 4-5: Fs [0,48K)
//   phase 6:   R  [0,32K)
// ----------------------------------------------------------------------------
__global__ void __launch_bounds__(TPB, 4) __cluster_dims__(2, 1, 1)
main_kernel(const float* __restrict__ X0,
            const float* __restrict__ t,
            const float* __restrict__ Wc_b,
            const float* __restrict__ w,
            float* __restrict__ V) {

    extern __shared__ float smem[];
    float* Xs    = smem;                     // [128 i_local][8 tok]
    u64*   E     = (u64*)(smem + 1024);      // [4 pair][2 ih][128 q]
    u64*   Epeer = (u64*)(smem + 3072);      // [4 slot][128 q]
    float* Fs    = smem;                     // [1536 f][8 tok]
    u64*   R     = (u64*)smem;               // [32 fs][128 col]

    const int tid = threadIdx.x;
    uint32_t rank;
    asm("mov.u32 %0, %%cluster_ctarank;" : "=r"(rank));
    const int tile = blockIdx.x >> 1;
    const int h    = blockIdx.x & 1;         // == rank
    const int g0   = tile * TOKB;
    const float tb = t[g0 >> 10];

    // ---- Phase 1: load + transpose this block's X i-half (4KB) ----------
    {
        int tok = tid >> 5;
        int seg = tid & 31;                  // 32 segs x 4 i's
        float4 v = *(const float4*)(X0 + (size_t)(g0 + tok) * D_INF + h * 128 + seg * 4);
        int i0 = seg * 4;
        Xs[(i0 + 0) * TOKB + tok] = v.x;
        Xs[(i0 + 1) * TOKB + tok] = v.y;
        Xs[(i0 + 2) * TOKB + tok] = v.z;
        Xs[(i0 + 3) * TOKB + tok] = v.w;
    }
    __syncthreads();

    // ---- Phase 2: GEMM1 over 128 i's (thread = ih x q, 8 tok) -----------
    {
        const int ih = tid >> 7;             // 0/1: 64 i's each
        const int q  = tid & (NQ - 1);
        u64 acc[4] = {0ULL, 0ULL, 0ULL, 0ULL};
        const float* wp = g_WcT + (h * 128 + ih * 64) * NQ + q;
        const float* xb = Xs + (ih * 64) * TOKB;
        #pragma unroll 8
        for (int s = 0; s < 64; s++) {
            float wv = __ldg(wp + s * NQ);
            u64 wd = pack2(wv, wv);
            ulonglong2 xa = *(const ulonglong2*)(xb + s * TOKB);
            ulonglong2 xc = *(const ulonglong2*)(xb + s * TOKB + 4);
            acc[0] = fma2(xa.x, wd, acc[0]);
            acc[1] = fma2(xa.y, wd, acc[1]);
            acc[2] = fma2(xc.x, wd, acc[2]);
            acc[3] = fma2(xc.y, wd, acc[3]);
        }
        #pragma unroll
        for (int p = 0; p < 4; p++)
            E[(p * 2 + ih) * NQ + q] = acc[p];
    }
    __syncthreads();

    // ---- Phase 3: local ih-reduce, DSMEM push to peer, cluster sync -----
    u64 s0, s1;
    {
        const int q  = tid & (NQ - 1);
        const int th = tid >> 7;             // pairs 2th, 2th+1 (tokens 4th..4th+3)
        s0 = add2(E[((2 * th + 0) * 2 + 0) * NQ + q], E[((2 * th + 0) * 2 + 1) * NQ + q]);
        s1 = add2(E[((2 * th + 1) * 2 + 0) * NQ + q], E[((2 * th + 1) * 2 + 1) * NQ + q]);

        // push partials into the PEER block's Epeer at the same offsets
        uint32_t a0 = smem_u32(&Epeer[(th * 2 + 0) * NQ + q]);
        uint32_t a1 = smem_u32(&Epeer[(th * 2 + 1) * NQ + q]);
        uint32_t peer = rank ^ 1u;
        uint32_t r0, r1;
        asm volatile("mapa.shared::cluster.u32 %0, %1, %2;" : "=r"(r0) : "r"(a0), "r"(peer));
        asm volatile("mapa.shared::cluster.u32 %0, %1, %2;" : "=r"(r1) : "r"(a1), "r"(peer));
        asm volatile("st.shared::cluster.u64 [%0], %1;" :: "r"(r0), "l"(s0) : "memory");
        asm volatile("st.shared::cluster.u64 [%0], %1;" :: "r"(r1), "l"(s1) : "memory");
    }
    asm volatile("barrier.cluster.arrive.aligned;" ::: "memory");
    asm volatile("barrier.cluster.wait.aligned;" ::: "memory");

    // ---- Phase 4: total angles, sincos + harmonics -> full F ------------
    {
        const int q  = tid & (NQ - 1);
        const int th = tid >> 7;
        float init = fmaf(w[q], tb, Wc_b[q]);
        u64 bi = pack2(init, init);
        u64 tot0 = add2(add2(s0, Epeer[(th * 2 + 0) * NQ + q]), bi);
        u64 tot1 = add2(add2(s1, Epeer[(th * 2 + 1) * NQ + q]), bi);
        float2 a01 = unpack2(tot0);
        float2 a23 = unpack2(tot1);
        float ang[4] = {a01.x, a01.y, a23.x, a23.y};
        __syncthreads();                     // Epeer reads done; Fs may clobber

        float sv[4], cv[4], sk[4], ck[4];
        #pragma unroll
        for (int j = 0; j < 4; j++) {
            float nr = rintf(ang[j] * 0.15915494309189535f);
            float ar = fmaf(nr, -6.283185307179586f, ang[j]);
            __sincosf(ar, &sv[j], &cv[j]);
            sk[j] = sv[j]; ck[j] = cv[j];
        }
        float* base = Fs + q * TOKB + th * 4;
        #pragma unroll
        for (int k = 0; k < NK; k++) {
            *(float4*)(base + (k * NQ) * TOKB)        = make_float4(sk[0], sk[1], sk[2], sk[3]);
            *(float4*)(base + ((k + NK) * NQ) * TOKB) = make_float4(ck[0], ck[1], ck[2], ck[3]);
            #pragma unroll
            for (int j = 0; j < 4; j++) {
                float ns = fmaf(sk[j], cv[j], ck[j] * sv[j]);
                float nc = fmaf(ck[j], cv[j], -sk[j] * sv[j]);
                sk[j] = ns; ck[j] = nc;
            }
        }
    }
    __syncthreads();

    // ---- Phase 5: GEMM2 over this block's 32 d-columns ------------------
    const int fs = tid >> 3;                 // 0..31, f = j*32 + fs
    const int dg = tid & 7;                  // d = h*32 + dg*4 + dd
    u64 acc[16];                             // [pair 4][dd 4]
    #pragma unroll
    for (int k = 0; k < 16; k++) acc[k] = 0ULL;

    const float* w2base = g_W2 + h * 32 + dg * 4;
    #pragma unroll 4
    for (int j = 0; j < NFEAT / 32; j++) {
        int f = j * 32 + fs;
        const float* frow = Fs + f * TOKB;
        ulonglong2 f01 = *(const ulonglong2*)frow;
        ulonglong2 f23 = *(const ulonglong2*)(frow + 4);
        float4 wv = __ldg((const float4*)(w2base + f * D_OUTF));
        u64 fp[4] = {f01.x, f01.y, f23.x, f23.y};
        float wa[4] = {wv.x, wv.y, wv.z, wv.w};
        #pragma unroll
        for (int dd = 0; dd < 4; dd++) {
            u64 wd = pack2(wa[dd], wa[dd]);
            #pragma unroll
            for (int p = 0; p < 4; p++)
                acc[p * 4 + dd] = fma2(fp[p], wd, acc[p * 4 + dd]);
        }
    }

    // ---- Phase 6: reduce over 32 f-slices (swizzled), store V -----------
    __syncthreads();
    #pragma unroll
    for (int p = 0; p < 4; p++)
        #pragma unroll
        for (int dd = 0; dd < 4; dd++) {
            int col = (p * 32 + dg * 4 + dd + fs * 4) & 127;
            R[fs * 128 + col] = acc[p * 4 + dd];
        }
    __syncthreads();

    if (tid < 128) {
        int od = tid;
        u64 s = 0ULL;
        #pragma unroll
        for (int j = 0; j < 32; j++)
            s = add2(s, R[j * 128 + ((od + j * 4) & 127)]);
        float2 v = unpack2(s);
        int p = od >> 5;
        int c = od & 31;
        float* vp = V + (size_t)(g0 + 2 * p) * D_OUTF + h * 32 + c;
        vp[0]      = v.x;
        vp[D_OUTF] = v.y;
    }
}

// ----------------------------------------------------------------------------
extern "C" void kernel_launch(void* const* d_in, const int* in_sizes, int n_in,
                              void* d_out, int out_size) {
    const float* X0   = (const float*)d_in[0];
    const float* t    = (const float*)d_in[1];
    const float* Wc_w = (const float*)d_in[2];
    const float* Wc_b = (const float*)d_in[3];
    const float* w    = (const float*)d_in[4];
    const float* A    = (const float*)d_in[5];
    const float* Bp   = (const float*)d_in[6];
    float* V = (float*)d_out;

    const int smem_bytes = 49152;
    cudaFuncSetAttribute(main_kernel, cudaFuncAttributeMaxDynamicSharedMemorySize, smem_bytes);

    prep_kernel<<<192, 256>>>(Wc_w, A, Bp);
    main_kernel<<<512, TPB, smem_bytes>>>(X0, t, Wc_b, w, V);
}